// round 15
// baseline (speedup 1.0000x reference)
#include <cuda_runtime.h>
#include <math.h>

#define BB   16
#define HH   512
#define WW   512
#define HWC  (HH*WW)
#define BHWC (BB*HWC)
#define NSIG 3
#define NIMG (NSIG*BB)
#define WPR  16          // 32-bit words per row (512/32)
#define WPI  (HH*WPR)    // words per image = 8192

// ---------------- scratch (device globals; no allocation) ----------------
__device__ float  g_gray[BHWC];
__device__ float  g_t1[NSIG*BHWC];
__device__ float  g_t2[NSIG*BHWC];
__device__ unsigned g_Sb[NIMG*WPI];
__device__ unsigned g_Wb[NIMG*WPI];
__device__ unsigned g_Eb[NIMG*WPI];
__device__ float g_hA[16*BHWC];
__device__ float g_hB[16*BHWC];

struct Coefs { float k[3][5]; };

// 5-tap NON-FMA left-assoc chain (XLA:CPU direct conv emitter: separate mul+add)
__device__ __forceinline__ float tap5(const float* k, float v0, float v1, float v2,
                                      float v3, float v4) {
    float t = __fmul_rn(k[0], v0);
    t = __fadd_rn(t, __fmul_rn(k[1], v1));
    t = __fadd_rn(t, __fmul_rn(k[2], v2));
    t = __fadd_rn(t, __fmul_rn(k[3], v3));
    t = __fadd_rn(t, __fmul_rn(k[4], v4));
    return t;
}

// ---------------- gray = 0.299 r + 0.587 g + 0.114 b (uncontracted, left-assoc) ----------------
__global__ void k_gray(const float* __restrict__ x) {
    int i = blockIdx.x * 256 + threadIdx.x;
    if (i >= BHWC) return;
    int b = i / HWC, p = i % HWC;
    const float* xb = x + (size_t)b * 3 * HWC;
    float r = xb[p], g = xb[HWC + p], bl = xb[2 * HWC + p];
    g_gray[i] = __fadd_rn(__fadd_rn(__fmul_rn(0.299f, r), __fmul_rn(0.587f, g)),
                          __fmul_rn(0.114f, bl));
}

// ---------------- separable 5-tap gaussian (SAME, zero pad), fp32 ----------------
__global__ void k_blurV(const float* __restrict__ in, float* __restrict__ out,
                        Coefs cf, int fixedSel, int inIsGray) {
    int z = blockIdx.y;
    int idx = blockIdx.x * 256 + threadIdx.x;
    int y = idx >> 9;
    const float* src = in + (size_t)(inIsGray ? (z & 15) : z) * HWC;
    int sel = (fixedSel >= 0) ? fixedSel : (z >> 4);
    const float* k = cf.k[sel];
    float v0 = (y >= 2)      ? src[idx - 2 * WW] : 0.f;
    float v1 = (y >= 1)      ? src[idx - WW]     : 0.f;
    float v2 = src[idx];
    float v3 = (y <= HH - 2) ? src[idx + WW]     : 0.f;
    float v4 = (y <= HH - 3) ? src[idx + 2 * WW] : 0.f;
    out[(size_t)z * HWC + idx] = tap5(k, v0, v1, v2, v3, v4);
}

__global__ void k_blurH(const float* __restrict__ in, float* __restrict__ out,
                        Coefs cf, int fixedSel) {
    int z = blockIdx.y;
    int idx = blockIdx.x * 256 + threadIdx.x;
    int x = idx & 511;
    const float* src = in + (size_t)z * HWC;
    int sel = (fixedSel >= 0) ? fixedSel : (z >> 4);
    const float* k = cf.k[sel];
    float v0 = (x >= 2)      ? src[idx - 2] : 0.f;
    float v1 = (x >= 1)      ? src[idx - 1] : 0.f;
    float v2 = src[idx];
    float v3 = (x <= WW - 2) ? src[idx + 1] : 0.f;
    float v4 = (x <= WW - 3) ? src[idx + 2] : 0.f;
    out[(size_t)z * HWC + idx] = tap5(k, v0, v1, v2, v3, v4);
}

// ---------------- sobel (exact-product taps; FMA == mul/add bitwise) ----------------
__device__ __forceinline__ float sobel_gx(float a00, float a02, float a10, float a12,
                                          float a20, float a22) {
    float t = __fadd_rn(-a00, a02);
    t = __fmaf_rn(-2.f, a10, t);
    t = __fmaf_rn(2.f, a12, t);
    t = __fsub_rn(t, a20);
    t = __fadd_rn(t, a22);
    return t;
}
__device__ __forceinline__ float sobel_gy(float a00, float a01, float a02,
                                          float a20, float a21, float a22) {
    float t = -a00;
    t = __fmaf_rn(-2.f, a01, t);
    t = __fsub_rn(t, a02);
    t = __fadd_rn(t, a20);
    t = __fmaf_rn(2.f, a21, t);
    t = __fadd_rn(t, a22);
    return t;
}

// uncontracted magnitude: sqrt(add(add(mul(gx,gx), mul(gy,gy)), 1e-12))
__device__ __forceinline__ float mag_of(float gx, float gy) {
    float s2 = __fadd_rn(__fadd_rn(__fmul_rn(gx, gx), __fmul_rn(gy, gy)), 1e-12f);
    return __fsqrt_rn(s2);
}

// correctly-rounded atan2f (double atan2 -> fp32), then faithful divide + rintf
__device__ __forceinline__ int quant_dir(float gyf, float gxf) {
    float ang = (float)atan2((double)gyf, (double)gxf);
    float rq = rintf(__fdiv_rn(ang, 0.7853981633974483f));
    return ((int)rq) & 3;
}

// ---------------- sobel + mag + NMS + double threshold -> bitmaps ----------------
__global__ void k_sobel_nms_bits(const float* __restrict__ t,
                                 unsigned* __restrict__ Sb, unsigned* __restrict__ Wb) {
    __shared__ float a[12][36];
    __shared__ float mg[10][34];
    int z = blockIdx.z;
    int x0 = blockIdx.x * 32, y0 = blockIdx.y * 8;
    int tid = threadIdx.y * 32 + threadIdx.x;
    const float* src = t + (size_t)z * HWC;

    for (int i = tid; i < 12 * 36; i += 256) {
        int r = i / 36, c = i % 36;
        int y = y0 + r - 2, x = x0 + c - 2;
        a[r][c] = ((unsigned)y < HH && (unsigned)x < WW) ? src[y * WW + x] : 0.f;
    }
    __syncthreads();

    for (int i = tid; i < 10 * 34; i += 256) {
        int r = i / 34, c = i % 34;
        int y = y0 + r - 1, x = x0 + c - 1;
        float m = 0.f;
        if ((unsigned)y < HH && (unsigned)x < WW) {
            float a00 = a[r][c],     a01 = a[r][c + 1],     a02 = a[r][c + 2];
            float a10 = a[r + 1][c],                        a12 = a[r + 1][c + 2];
            float a20 = a[r + 2][c], a21 = a[r + 2][c + 1], a22 = a[r + 2][c + 2];
            float gx = sobel_gx(a00, a02, a10, a12, a20, a22);
            float gy = sobel_gy(a00, a01, a02, a20, a21, a22);
            m = mag_of(gx, gy);
        }
        mg[r][c] = m;
    }
    __syncthreads();

    int tx = threadIdx.x, ty = threadIdx.y;
    float a00 = a[ty + 1][tx + 1], a01 = a[ty + 1][tx + 2], a02 = a[ty + 1][tx + 3];
    float a10 = a[ty + 2][tx + 1],                          a12 = a[ty + 2][tx + 3];
    float a20 = a[ty + 3][tx + 1], a21 = a[ty + 3][tx + 2], a22 = a[ty + 3][tx + 3];
    float gx = sobel_gx(a00, a02, a10, a12, a20, a22);
    float gy = sobel_gy(a00, a01, a02, a20, a21, a22);
    int q = quant_dir(gy, gx);

    int r = ty + 1, c = tx + 1;
    float m = mg[r][c];
    float na, nb;
    if (q == 0)      { na = mg[r][c + 1];     nb = mg[r][c - 1]; }
    else if (q == 1) { na = mg[r - 1][c + 1]; nb = mg[r + 1][c - 1]; }
    else if (q == 2) { na = mg[r - 1][c];     nb = mg[r + 1][c]; }
    else             { na = mg[r - 1][c - 1]; nb = mg[r + 1][c + 1]; }
    float nms = (m >= na && m >= nb) ? m : 0.f;
    int sv = (nms > 0.2f) ? 2 : ((nms > 0.1f) ? 1 : 0);

    unsigned sw = __ballot_sync(0xffffffffu, sv == 2);
    unsigned ww = __ballot_sync(0xffffffffu, sv == 1);
    if (tx == 0) {
        int w = (y0 + ty) * WPR + (x0 >> 5);
        Sb[(size_t)z * WPI + w] = sw;
        Wb[(size_t)z * WPI + w] = ww;
    }
}

// ---------------- hysteresis: exact per-image global fixpoint on bitmaps ----------------
__global__ void __launch_bounds__(512) k_hyst(const unsigned* __restrict__ Sb,
                                              const unsigned* __restrict__ Wb,
                                              unsigned* __restrict__ Eb) {
    __shared__ unsigned sS[512 * WPR];
    __shared__ int s_ch;
    int z = blockIdx.x, t = threadIdx.x;   // t = row
    unsigned S[WPR], W[WPR];
    const unsigned* s0 = Sb + (size_t)z * WPI;
    const unsigned* w0 = Wb + (size_t)z * WPI;
#pragma unroll
    for (int c = 0; c < WPR; c++) {
        S[c] = s0[t * WPR + c];
        W[c] = w0[t * WPR + c];
        sS[t * WPR + c] = S[c];
    }
    __syncthreads();

    for (int iter = 0; iter < 4096; iter++) {
        if (t == 0) s_ch = 0;
        __syncthreads();

        // seeds: weak pixels 8-adjacent to a strong pixel
        unsigned F[WPR];
        {
            unsigned u_prev = 0, u_cur = (t > 0) ? sS[(t - 1) * WPR] : 0u;
            unsigned d_prev = 0, d_cur = (t < 511) ? sS[(t + 1) * WPR] : 0u;
            unsigned s_prev = 0, s_cur = S[0];
#pragma unroll
            for (int c = 0; c < WPR; c++) {
                unsigned u_next = (c < WPR - 1) ? ((t > 0) ? sS[(t - 1) * WPR + c + 1] : 0u) : 0u;
                unsigned d_next = (c < WPR - 1) ? ((t < 511) ? sS[(t + 1) * WPR + c + 1] : 0u) : 0u;
                unsigned s_next = (c < WPR - 1) ? S[c + 1] : 0u;
                unsigned du = u_cur | (u_cur << 1) | (u_cur >> 1) | (u_prev >> 31) | (u_next << 31);
                unsigned dd = d_cur | (d_cur << 1) | (d_cur >> 1) | (d_prev >> 31) | (d_next << 31);
                unsigned ds = (s_cur << 1) | (s_cur >> 1) | (s_prev >> 31) | (s_next << 31);
                F[c] = W[c] & (s_cur | du | dd | ds);
                u_prev = u_cur; u_cur = u_next;
                d_prev = d_cur; d_cur = d_next;
                s_prev = s_cur; s_cur = s_next;
            }
        }

        // horizontal run fill, increasing-x (carry trick)
        {
            unsigned carry = 0;
#pragma unroll
            for (int c = 0; c < WPR; c++) {
                unsigned w = W[c];
                unsigned sd = F[c] | (carry & w & 1u);
                unsigned fill = (w ^ (w + sd)) & w;
                F[c] = sd | fill;
                carry = (fill >> 31) & 1u;
            }
        }
        // decreasing-x (bit-reverse + carry trick)
        {
            unsigned carry = 0;
#pragma unroll
            for (int c = WPR - 1; c >= 0; c--) {
                unsigned rw = __brev(W[c]);
                unsigned rsd = __brev(F[c]) | (carry & rw & 1u);
                unsigned rfill = (rw ^ (rw + rsd)) & rw;
                F[c] = __brev(rsd | rfill);
                carry = (rfill >> 31) & 1u;
            }
        }

        bool ch = false;
#pragma unroll
        for (int c = 0; c < WPR; c++) {
            unsigned ns = S[c] | F[c];
            if (ns != S[c]) { S[c] = ns; ch = true; }
        }
        if (ch) {
            s_ch = 1;
#pragma unroll
            for (int c = 0; c < WPR; c++) sS[t * WPR + c] = S[c];
        }
        __syncthreads();
        bool done = (s_ch == 0);
        __syncthreads();
        if (done) break;
    }

    unsigned* e0 = Eb + (size_t)z * WPI;
#pragma unroll
    for (int c = 0; c < WPR; c++) e0[t * WPR + c] = S[c];
}

// ---------------- combined = max over sigmas, bitmap -> float ----------------
__global__ void k_combined_bits(const unsigned* __restrict__ Eb, float* __restrict__ outc) {
    int gid = blockIdx.x * 256 + threadIdx.x;
    int warp = gid >> 5, lane = gid & 31;
    if (warp >= BB * WPI) return;
    int b = warp / WPI, w = warp % WPI;
    unsigned e = Eb[(size_t)(0 * BB + b) * WPI + w]
               | Eb[(size_t)(1 * BB + b) * WPI + w]
               | Eb[(size_t)(2 * BB + b) * WPI + w];
    outc[(size_t)b * HWC + w * 32 + lane] = ((e >> lane) & 1u) ? 1.f : 0.f;
}

// ---------------- generic 3x3 conv (SAME zero pad), tiled ----------------
template<int CIN, int COUT, int ACT>
__global__ void __launch_bounds__(128)
conv3x3_k(const float* __restrict__ in, int inChanStride, int inBatchStride,
          const float* __restrict__ wgt, const float* __restrict__ bias,
          float* __restrict__ outA, float* __restrict__ outB,
          const float* __restrict__ mask, const float* __restrict__ deep) {
    __shared__ float smIn[CIN][18][34];
    __shared__ float smW[COUT * CIN * 9];

    int b = blockIdx.z;
    int x0 = blockIdx.x * 32, y0 = blockIdx.y * 16;
    int tid = threadIdx.y * 32 + threadIdx.x;
    const float* inB = in + (size_t)b * inBatchStride;

    for (int i = tid; i < CIN * 18 * 34; i += 128) {
        int ci = i / (18 * 34);
        int rem = i % (18 * 34);
        int r = rem / 34, c = rem % 34;
        int y = y0 + r - 1, x = x0 + c - 1;
        float v = 0.f;
        if ((unsigned)y < HH && (unsigned)x < WW)
            v = inB[(size_t)ci * inChanStride + y * WW + x];
        smIn[ci][r][c] = v;
    }
    for (int i = tid; i < COUT * CIN * 9; i += 128) smW[i] = wgt[i];
    __syncthreads();

    float acc[4][COUT];
#pragma unroll
    for (int p = 0; p < 4; p++)
#pragma unroll
        for (int co = 0; co < COUT; co++) acc[p][co] = 0.f;

    int tx = threadIdx.x;
    int ry = threadIdx.y * 4;

#pragma unroll 1
    for (int ci = 0; ci < CIN; ci++) {
#pragma unroll
        for (int kx = 0; kx < 3; kx++) {
            float v[6];
#pragma unroll
            for (int j = 0; j < 6; j++) v[j] = smIn[ci][ry + j][tx + kx];
#pragma unroll
            for (int ky = 0; ky < 3; ky++) {
#pragma unroll
                for (int co = 0; co < COUT; co++) {
                    float w = smW[((co * CIN + ci) * 3 + ky) * 3 + kx];
#pragma unroll
                    for (int p = 0; p < 4; p++)
                        acc[p][co] = fmaf(v[p + ky], w, acc[p][co]);
                }
            }
        }
    }

#pragma unroll
    for (int p = 0; p < 4; p++) {
        int y = y0 + ry + p;
        int idx = y * WW + (x0 + tx);
#pragma unroll
        for (int co = 0; co < COUT; co++) {
            float vv = acc[p][co] + __ldg(&bias[co]);
            if (ACT == 0) {
                vv = (vv >= 0.f) ? vv : 0.2f * vv;
                outA[((size_t)b * COUT + co) * HWC + idx] = vv;
            } else if (ACT == 2) {
                float s = 1.f / (1.f + expf(-vv));
                outA[(size_t)b * HWC + idx] = s;
                outB[(size_t)b * 2 * HWC + HWC + idx] = s;
            } else if (ACT == 3) {
                float s = 1.f / (1.f + expf(-vv));
                float m = mask[(size_t)b * HWC + idx];
                float d = deep[(size_t)b * HWC + idx];
                float em = s * (1.f - m) + d * m * 0.5f;
                outA[(size_t)b * HWC + idx] = em;
                outB[(size_t)b * 2 * HWC + idx] = em;
            }
        }
    }
}

// ---------------- host launcher ----------------
extern "C" void kernel_launch(void* const* d_in, const int* in_sizes, int n_in,
                              void* d_out, int out_size) {
    const float* x    = (const float*)d_in[0];
    const float* mask = (const float*)d_in[1];
    const float* wd1 = (const float*)d_in[2];  const float* bd1 = (const float*)d_in[3];
    const float* wd2 = (const float*)d_in[4];  const float* bd2 = (const float*)d_in[5];
    const float* wd3 = (const float*)d_in[6];  const float* bd3 = (const float*)d_in[7];
    const float* wd4 = (const float*)d_in[8];  const float* bd4 = (const float*)d_in[9];
    const float* wr1 = (const float*)d_in[10]; const float* br1 = (const float*)d_in[11];
    const float* wr2 = (const float*)d_in[12]; const float* br2 = (const float*)d_in[13];
    const float* wr3 = (const float*)d_in[14]; const float* br3 = (const float*)d_in[15];

    float* out     = (float*)d_out;
    float* o_edge  = out;
    float* o_feat  = out + (size_t)BHWC;
    float* o_canny = out + (size_t)3 * BHWC;
    float* o_deep  = out + (size_t)4 * BHWC;

    float *p_gray, *p_t1, *p_t2, *p_hA, *p_hB;
    unsigned *p_Sb, *p_Wb, *p_Eb;
    cudaGetSymbolAddress((void**)&p_gray, g_gray);
    cudaGetSymbolAddress((void**)&p_t1, g_t1);
    cudaGetSymbolAddress((void**)&p_t2, g_t2);
    cudaGetSymbolAddress((void**)&p_Sb, g_Sb);
    cudaGetSymbolAddress((void**)&p_Wb, g_Wb);
    cudaGetSymbolAddress((void**)&p_Eb, g_Eb);
    cudaGetSymbolAddress((void**)&p_hA, g_hA);
    cudaGetSymbolAddress((void**)&p_hB, g_hB);

    // gaussian coefficients, numpy float32 semantics
    Coefs cf;
    const double sig[3] = {0.5, 1.0, 2.0};
    for (int s = 0; s < 3; s++) {
        float e[5];
        for (int i = 0; i < 5; i++) {
            float r = (float)i - 2.0f;
            float denom = 2.0f * (float)sig[s] * (float)sig[s];
            float ex = -(r * r) / denom;
            e[i] = (float)exp((double)ex);
        }
        float sum = (((e[0] + e[1]) + e[2]) + e[3]) + e[4];
        for (int i = 0; i < 5; i++) cf.k[s][i] = e[i] / sum;
    }

    // ---- Canny path (3 sigmas batched as 48 images), fp32 ----
    k_gray<<<BHWC / 256, 256>>>(x);
    dim3 bg(HWC / 256, NIMG);
    k_blurV<<<bg, 256>>>(p_gray, p_t1, cf, -1, 1);  // blur(gray, sigma) V
    k_blurH<<<bg, 256>>>(p_t1, p_t2, cf, -1);       // blur(gray, sigma) H
    k_blurV<<<bg, 256>>>(p_t2, p_t1, cf, 1, 0);     // canny internal blur sigma=1 V
    k_blurH<<<bg, 256>>>(p_t1, p_t2, cf, 1);        // canny internal blur sigma=1 H
    k_sobel_nms_bits<<<dim3(WW / 32, HH / 8, NIMG), dim3(32, 8)>>>(p_t2, p_Sb, p_Wb);
    k_hyst<<<NIMG, 512>>>(p_Sb, p_Wb, p_Eb);
    k_combined_bits<<<(BB * WPI * 32) / 256, 256>>>(p_Eb, o_canny);

    // ---- deep conv stack ----
    dim3 cb(32, 4), cg(WW / 32, HH / 16, BB);
    conv3x3_k<3, 16, 0><<<cg, cb>>>(x,     HWC, 3 * HWC,  wd1, bd1, p_hA, nullptr, nullptr, nullptr);
    conv3x3_k<16, 16, 0><<<cg, cb>>>(p_hA, HWC, 16 * HWC, wd2, bd2, p_hB, nullptr, nullptr, nullptr);
    conv3x3_k<16, 8, 0><<<cg, cb>>>(p_hB,  HWC, 16 * HWC, wd3, bd3, p_hA, nullptr, nullptr, nullptr);
    conv3x3_k<8, 1, 2><<<cg, cb>>>(p_hA,   HWC, 8 * HWC,  wd4, bd4, o_deep, o_feat, nullptr, nullptr);

    // ---- refine stack: input channels = [combined_canny, deep_edges] ----
    conv3x3_k<2, 8, 0><<<cg, cb>>>(o_canny, BHWC, HWC,    wr1, br1, p_hB, nullptr, nullptr, nullptr);
    conv3x3_k<8, 4, 0><<<cg, cb>>>(p_hB,   HWC, 8 * HWC,  wr2, br2, p_hA, nullptr, nullptr, nullptr);
    conv3x3_k<4, 1, 3><<<cg, cb>>>(p_hA,   HWC, 4 * HWC,  wr3, br3, o_edge, o_feat, mask, o_deep);
}

// round 17
// speedup vs baseline: 1.3119x; 1.3119x over previous
#include <cuda_runtime.h>
#include <math.h>

#define BB   16
#define HH   512
#define WW   512
#define HWC  (HH*WW)
#define BHWC (BB*HWC)
#define NSIG 3
#define NIMG (NSIG*BB)
#define WPR  16          // 32-bit words per row (512/32)
#define WPI  (HH*WPR)    // words per image = 8192
#define HT   44          // fused tile with +/-6 halo

// ---------------- scratch (device globals; no allocation) ----------------
__device__ unsigned g_Sb[NIMG*WPI];
__device__ unsigned g_Wb[NIMG*WPI];
__device__ unsigned g_Eb[NIMG*WPI];
__device__ float g_hA[16*BHWC];
__device__ float g_hB[16*BHWC];
__device__ float g_wt[4752];   // transposed conv weights, co-contiguous

struct Coefs { float k[3][5]; };

// 5-tap NON-FMA left-assoc chain (frozen: this is the bit-exact recipe)
__device__ __forceinline__ float tap5(const float* k, float v0, float v1, float v2,
                                      float v3, float v4) {
    float t = __fmul_rn(k[0], v0);
    t = __fadd_rn(t, __fmul_rn(k[1], v1));
    t = __fadd_rn(t, __fmul_rn(k[2], v2));
    t = __fadd_rn(t, __fmul_rn(k[3], v3));
    t = __fadd_rn(t, __fmul_rn(k[4], v4));
    return t;
}

__device__ __forceinline__ float sobel_gx(float a00, float a02, float a10, float a12,
                                          float a20, float a22) {
    float t = __fadd_rn(-a00, a02);
    t = __fmaf_rn(-2.f, a10, t);
    t = __fmaf_rn(2.f, a12, t);
    t = __fsub_rn(t, a20);
    t = __fadd_rn(t, a22);
    return t;
}
__device__ __forceinline__ float sobel_gy(float a00, float a01, float a02,
                                          float a20, float a21, float a22) {
    float t = -a00;
    t = __fmaf_rn(-2.f, a01, t);
    t = __fsub_rn(t, a02);
    t = __fadd_rn(t, a20);
    t = __fmaf_rn(2.f, a21, t);
    t = __fadd_rn(t, a22);
    return t;
}
__device__ __forceinline__ float mag_of(float gx, float gy) {
    float s2 = __fadd_rn(__fadd_rn(__fmul_rn(gx, gx), __fmul_rn(gy, gy)), 1e-12f);
    return __fsqrt_rn(s2);
}
__device__ __forceinline__ int quant_dir(float gyf, float gxf) {
    float ang = (float)atan2((double)gyf, (double)gxf);
    float rq = rintf(__fdiv_rn(ang, 0.7853981633974483f));
    return ((int)rq) & 3;
}

// ---------------- fused: gray -> V -> H -> V -> H -> sobel -> NMS -> bitmaps ----------------
__global__ void __launch_bounds__(256) k_canny_front(const float* __restrict__ x,
                                                     unsigned* __restrict__ Sb,
                                                     unsigned* __restrict__ Wb, Coefs cf) {
    __shared__ float A[HT * HT];
    __shared__ float B[HT * HT];
    int z = blockIdx.z;
    int b = z & 15;
    int x0 = blockIdx.x * 32, y0 = blockIdx.y * 32;
    int tid = threadIdx.x;
    const float* xb = x + (size_t)b * 3 * HWC;
    const float* kS = cf.k[z >> 4];
    const float* k1 = cf.k[1];

    // gray over [y0-6, y0+37] x [x0-6, x0+37]
    for (int i = tid; i < HT * HT; i += 256) {
        int r = i / HT, c = i % HT;
        int y = y0 + r - 6, xx = x0 + c - 6;
        float v = 0.f;
        if ((unsigned)y < HH && (unsigned)xx < WW) {
            int p = y * WW + xx;
            float rr = xb[p], gg = xb[HWC + p], bb = xb[2 * HWC + p];
            v = __fadd_rn(__fadd_rn(__fmul_rn(0.299f, rr), __fmul_rn(0.587f, gg)),
                          __fmul_rn(0.114f, bb));
        }
        A[i] = v;
    }
    __syncthreads();
    // t1 = Vblur_sig: r in [2,41], all 44 cols -> B
    for (int i = tid; i < 40 * HT; i += 256) {
        int r = i / HT + 2, c = i % HT;
        int y = y0 + r - 6, xx = x0 + c - 6;
        float v = 0.f;
        if ((unsigned)y < HH && (unsigned)xx < WW)
            v = tap5(kS, A[(r - 2) * HT + c], A[(r - 1) * HT + c], A[r * HT + c],
                     A[(r + 1) * HT + c], A[(r + 2) * HT + c]);
        B[r * HT + c] = v;
    }
    __syncthreads();
    // t2 = Hblur_sig: r,c in [2,41] -> A
    for (int i = tid; i < 40 * 40; i += 256) {
        int r = i / 40 + 2, c = i % 40 + 2;
        int y = y0 + r - 6, xx = x0 + c - 6;
        float v = 0.f;
        if ((unsigned)y < HH && (unsigned)xx < WW)
            v = tap5(kS, B[r * HT + c - 2], B[r * HT + c - 1], B[r * HT + c],
                     B[r * HT + c + 1], B[r * HT + c + 2]);
        A[r * HT + c] = v;
    }
    __syncthreads();
    // t3 = Vblur_1: r in [4,39], c in [2,41] -> B
    for (int i = tid; i < 36 * 40; i += 256) {
        int r = i / 40 + 4, c = i % 40 + 2;
        int y = y0 + r - 6, xx = x0 + c - 6;
        float v = 0.f;
        if ((unsigned)y < HH && (unsigned)xx < WW)
            v = tap5(k1, A[(r - 2) * HT + c], A[(r - 1) * HT + c], A[r * HT + c],
                     A[(r + 1) * HT + c], A[(r + 2) * HT + c]);
        B[r * HT + c] = v;
    }
    __syncthreads();
    // t4 = Hblur_1: r,c in [4,39] -> A
    for (int i = tid; i < 36 * 36; i += 256) {
        int r = i / 36 + 4, c = i % 36 + 4;
        int y = y0 + r - 6, xx = x0 + c - 6;
        float v = 0.f;
        if ((unsigned)y < HH && (unsigned)xx < WW)
            v = tap5(k1, B[r * HT + c - 2], B[r * HT + c - 1], B[r * HT + c],
                     B[r * HT + c + 1], B[r * HT + c + 2]);
        A[r * HT + c] = v;
    }
    __syncthreads();
    // mag: r,c in [5,38] -> B
    for (int i = tid; i < 34 * 34; i += 256) {
        int r = i / 34 + 5, c = i % 34 + 5;
        int y = y0 + r - 6, xx = x0 + c - 6;
        float m = 0.f;
        if ((unsigned)y < HH && (unsigned)xx < WW) {
            float a00 = A[(r-1)*HT + c-1], a01 = A[(r-1)*HT + c], a02 = A[(r-1)*HT + c+1];
            float a10 = A[r*HT + c-1],                            a12 = A[r*HT + c+1];
            float a20 = A[(r+1)*HT + c-1], a21 = A[(r+1)*HT + c], a22 = A[(r+1)*HT + c+1];
            float gx = sobel_gx(a00, a02, a10, a12, a20, a22);
            float gy = sobel_gy(a00, a01, a02, a20, a21, a22);
            m = mag_of(gx, gy);
        }
        B[r * HT + c] = m;
    }
    __syncthreads();
    // final: NMS + thresholds + ballot -> bitmaps
    int w = tid >> 5, lane = tid & 31;
#pragma unroll
    for (int k2 = 0; k2 < 4; k2++) {
        int ry = w + 8 * k2;
        int r = ry + 6, c = lane + 6;
        float a00 = A[(r-1)*HT + c-1], a01 = A[(r-1)*HT + c], a02 = A[(r-1)*HT + c+1];
        float a10 = A[r*HT + c-1],                            a12 = A[r*HT + c+1];
        float a20 = A[(r+1)*HT + c-1], a21 = A[(r+1)*HT + c], a22 = A[(r+1)*HT + c+1];
        float gx = sobel_gx(a00, a02, a10, a12, a20, a22);
        float gy = sobel_gy(a00, a01, a02, a20, a21, a22);
        float m = B[r * HT + c];
        int sv = 0;
        if (m > 0.1f) {   // if m <= LOW, sv = 0 for any q: skip atan2
            int q = quant_dir(gy, gx);
            float na, nb;
            if (q == 0)      { na = B[r*HT + c+1];       nb = B[r*HT + c-1]; }
            else if (q == 1) { na = B[(r-1)*HT + c+1];   nb = B[(r+1)*HT + c-1]; }
            else if (q == 2) { na = B[(r-1)*HT + c];     nb = B[(r+1)*HT + c]; }
            else             { na = B[(r-1)*HT + c-1];   nb = B[(r+1)*HT + c+1]; }
            float nms = (m >= na && m >= nb) ? m : 0.f;
            sv = (nms > 0.2f) ? 2 : ((nms > 0.1f) ? 1 : 0);
        }
        unsigned sw = __ballot_sync(0xffffffffu, sv == 2);
        unsigned ww = __ballot_sync(0xffffffffu, sv == 1);
        if (lane == 0) {
            int word = (y0 + ry) * WPR + (x0 >> 5);
            Sb[(size_t)z * WPI + word] = sw;
            Wb[(size_t)z * WPI + word] = ww;
        }
    }
}

// ---------------- hysteresis: exact per-image global fixpoint on bitmaps ----------------
__global__ void __launch_bounds__(512) k_hyst(const unsigned* __restrict__ Sb,
                                              const unsigned* __restrict__ Wb,
                                              unsigned* __restrict__ Eb) {
    __shared__ unsigned sS[512 * WPR];
    __shared__ int s_ch;
    int z = blockIdx.x, t = threadIdx.x;
    unsigned S[WPR], W[WPR];
    const unsigned* s0 = Sb + (size_t)z * WPI;
    const unsigned* w0 = Wb + (size_t)z * WPI;
#pragma unroll
    for (int c = 0; c < WPR; c++) {
        S[c] = s0[t * WPR + c];
        W[c] = w0[t * WPR + c];
        sS[t * WPR + c] = S[c];
    }
    __syncthreads();

    for (int iter = 0; iter < 4096; iter++) {
        if (t == 0) s_ch = 0;
        __syncthreads();

        unsigned F[WPR];
        {
            unsigned u_prev = 0, u_cur = (t > 0) ? sS[(t - 1) * WPR] : 0u;
            unsigned d_prev = 0, d_cur = (t < 511) ? sS[(t + 1) * WPR] : 0u;
            unsigned s_prev = 0, s_cur = S[0];
#pragma unroll
            for (int c = 0; c < WPR; c++) {
                unsigned u_next = (c < WPR - 1) ? ((t > 0) ? sS[(t - 1) * WPR + c + 1] : 0u) : 0u;
                unsigned d_next = (c < WPR - 1) ? ((t < 511) ? sS[(t + 1) * WPR + c + 1] : 0u) : 0u;
                unsigned s_next = (c < WPR - 1) ? S[c + 1] : 0u;
                unsigned du = u_cur | (u_cur << 1) | (u_cur >> 1) | (u_prev >> 31) | (u_next << 31);
                unsigned dd = d_cur | (d_cur << 1) | (d_cur >> 1) | (d_prev >> 31) | (d_next << 31);
                unsigned ds = (s_cur << 1) | (s_cur >> 1) | (s_prev >> 31) | (s_next << 31);
                F[c] = W[c] & (s_cur | du | dd | ds);
                u_prev = u_cur; u_cur = u_next;
                d_prev = d_cur; d_cur = d_next;
                s_prev = s_cur; s_cur = s_next;
            }
        }
        {
            unsigned carry = 0;
#pragma unroll
            for (int c = 0; c < WPR; c++) {
                unsigned w = W[c];
                unsigned sd = F[c] | (carry & w & 1u);
                unsigned fill = (w ^ (w + sd)) & w;
                F[c] = sd | fill;
                carry = (fill >> 31) & 1u;
            }
        }
        {
            unsigned carry = 0;
#pragma unroll
            for (int c = WPR - 1; c >= 0; c--) {
                unsigned rw = __brev(W[c]);
                unsigned rsd = __brev(F[c]) | (carry & rw & 1u);
                unsigned rfill = (rw ^ (rw + rsd)) & rw;
                F[c] = __brev(rsd | rfill);
                carry = (rfill >> 31) & 1u;
            }
        }
        bool ch = false;
#pragma unroll
        for (int c = 0; c < WPR; c++) {
            unsigned ns = S[c] | F[c];
            if (ns != S[c]) { S[c] = ns; ch = true; }
        }
        if (ch) {
            s_ch = 1;
#pragma unroll
            for (int c = 0; c < WPR; c++) sS[t * WPR + c] = S[c];
        }
        __syncthreads();
        bool done = (s_ch == 0);
        __syncthreads();
        if (done) break;
    }

    unsigned* e0 = Eb + (size_t)z * WPI;
#pragma unroll
    for (int c = 0; c < WPR; c++) e0[t * WPR + c] = S[c];
}

// ---------------- combined = max over sigmas, bitmap -> float ----------------
__global__ void k_combined_bits(const unsigned* __restrict__ Eb, float* __restrict__ outc) {
    int gid = blockIdx.x * 256 + threadIdx.x;
    int warp = gid >> 5, lane = gid & 31;
    if (warp >= BB * WPI) return;
    int b = warp / WPI, w = warp % WPI;
    unsigned e = Eb[(size_t)(0 * BB + b) * WPI + w]
               | Eb[(size_t)(1 * BB + b) * WPI + w]
               | Eb[(size_t)(2 * BB + b) * WPI + w];
    outc[(size_t)b * HWC + w * 32 + lane] = ((e >> lane) & 1u) ? 1.f : 0.f;
}

// ---------------- weight transpose: [co][ci][ky][kx] -> [(ci*9+t)*CP + co] ----------------
__global__ void k_wtrans(const float* w0, const float* w1, const float* w2, const float* w3,
                         const float* w4, const float* w5, const float* w6, float* wt) {
    const float* ws[7] = {w0, w1, w2, w3, w4, w5, w6};
    const int cin[7]  = {3, 16, 16, 8, 2, 8, 4};
    const int cout[7] = {16, 16, 8, 1, 8, 4, 1};
    const int cp[7]   = {16, 16, 8, 4, 8, 4, 4};
    const int off[7]  = {0, 432, 2736, 3888, 4176, 4320, 4608};
    int l = blockIdx.x;
    const float* w = ws[l];
    int CIN = cin[l], COUT = cout[l], CP = cp[l];
    int total = CIN * 9 * CP;
    for (int i = threadIdx.x; i < total; i += 256) {
        int co = i % CP;
        int rest = i / CP;
        int ci = rest / 9, t = rest % 9;
        wt[off[l] + i] = (co < COUT) ? w[(co * CIN + ci) * 9 + t] : 0.f;
    }
}

// ---------------- generic 3x3 conv (SAME zero pad), vec4 weight loads ----------------
template<int CIN, int COUT, int CP, int ACT>
__global__ void __launch_bounds__(128)
conv3x3_k(const float* __restrict__ in, int inChanStride, int inBatchStride,
          const float* __restrict__ wt, const float* __restrict__ bias,
          float* __restrict__ outA, float* __restrict__ outB,
          const float* __restrict__ mask, const float* __restrict__ deep) {
    __shared__ float smIn[CIN][18][34];
    __shared__ __align__(16) float smW[CIN * 9 * CP];

    int b = blockIdx.z;
    int x0 = blockIdx.x * 32, y0 = blockIdx.y * 16;
    int tid = threadIdx.y * 32 + threadIdx.x;
    const float* inB = in + (size_t)b * inBatchStride;

    for (int i = tid; i < CIN * 18 * 34; i += 128) {
        int ci = i / (18 * 34);
        int rem = i % (18 * 34);
        int r = rem / 34, c = rem % 34;
        int y = y0 + r - 1, x = x0 + c - 1;
        float v = 0.f;
        if ((unsigned)y < HH && (unsigned)x < WW)
            v = inB[(size_t)ci * inChanStride + y * WW + x];
        smIn[ci][r][c] = v;
    }
    for (int i = tid; i < CIN * 9 * CP; i += 128) smW[i] = wt[i];
    __syncthreads();

    float acc[4][CP];
#pragma unroll
    for (int p = 0; p < 4; p++)
#pragma unroll
        for (int co = 0; co < CP; co++) acc[p][co] = 0.f;

    int tx = threadIdx.x;
    int ry = threadIdx.y * 4;

#pragma unroll 1
    for (int ci = 0; ci < CIN; ci++) {
#pragma unroll
        for (int kx = 0; kx < 3; kx++) {
            float v[6];
#pragma unroll
            for (int j = 0; j < 6; j++) v[j] = smIn[ci][ry + j][tx + kx];
#pragma unroll
            for (int ky = 0; ky < 3; ky++) {
#pragma unroll
                for (int c4 = 0; c4 < CP / 4; c4++) {
                    const float4 w4 = *(const float4*)&smW[(ci * 9 + ky * 3 + kx) * CP + c4 * 4];
#pragma unroll
                    for (int p = 0; p < 4; p++) {
                        float vv = v[p + ky];
                        acc[p][c4 * 4 + 0] = fmaf(vv, w4.x, acc[p][c4 * 4 + 0]);
                        acc[p][c4 * 4 + 1] = fmaf(vv, w4.y, acc[p][c4 * 4 + 1]);
                        acc[p][c4 * 4 + 2] = fmaf(vv, w4.z, acc[p][c4 * 4 + 2]);
                        acc[p][c4 * 4 + 3] = fmaf(vv, w4.w, acc[p][c4 * 4 + 3]);
                    }
                }
            }
        }
    }

#pragma unroll
    for (int p = 0; p < 4; p++) {
        int y = y0 + ry + p;
        int idx = y * WW + (x0 + tx);
#pragma unroll
        for (int co = 0; co < COUT; co++) {
            float vv = acc[p][co] + __ldg(&bias[co]);
            if (ACT == 0) {
                vv = (vv >= 0.f) ? vv : 0.2f * vv;
                outA[((size_t)b * COUT + co) * HWC + idx] = vv;
            } else if (ACT == 2) {
                float s = 1.f / (1.f + expf(-vv));
                outA[(size_t)b * HWC + idx] = s;
                outB[(size_t)b * 2 * HWC + HWC + idx] = s;
            } else if (ACT == 3) {
                float s = 1.f / (1.f + expf(-vv));
                float m = mask[(size_t)b * HWC + idx];
                float d = deep[(size_t)b * HWC + idx];
                float em = s * (1.f - m) + d * m * 0.5f;
                outA[(size_t)b * HWC + idx] = em;
                outB[(size_t)b * 2 * HWC + idx] = em;
            }
        }
    }
}

// ---------------- host launcher ----------------
extern "C" void kernel_launch(void* const* d_in, const int* in_sizes, int n_in,
                              void* d_out, int out_size) {
    const float* x    = (const float*)d_in[0];
    const float* mask = (const float*)d_in[1];
    const float* wd1 = (const float*)d_in[2];  const float* bd1 = (const float*)d_in[3];
    const float* wd2 = (const float*)d_in[4];  const float* bd2 = (const float*)d_in[5];
    const float* wd3 = (const float*)d_in[6];  const float* bd3 = (const float*)d_in[7];
    const float* wd4 = (const float*)d_in[8];  const float* bd4 = (const float*)d_in[9];
    const float* wr1 = (const float*)d_in[10]; const float* br1 = (const float*)d_in[11];
    const float* wr2 = (const float*)d_in[12]; const float* br2 = (const float*)d_in[13];
    const float* wr3 = (const float*)d_in[14]; const float* br3 = (const float*)d_in[15];

    float* out     = (float*)d_out;
    float* o_edge  = out;
    float* o_feat  = out + (size_t)BHWC;
    float* o_canny = out + (size_t)3 * BHWC;
    float* o_deep  = out + (size_t)4 * BHWC;

    float *p_hA, *p_hB, *p_wt;
    unsigned *p_Sb, *p_Wb, *p_Eb;
    cudaGetSymbolAddress((void**)&p_Sb, g_Sb);
    cudaGetSymbolAddress((void**)&p_Wb, g_Wb);
    cudaGetSymbolAddress((void**)&p_Eb, g_Eb);
    cudaGetSymbolAddress((void**)&p_hA, g_hA);
    cudaGetSymbolAddress((void**)&p_hB, g_hB);
    cudaGetSymbolAddress((void**)&p_wt, g_wt);

    // gaussian coefficients, numpy float32 semantics
    Coefs cf;
    const double sig[3] = {0.5, 1.0, 2.0};
    for (int s = 0; s < 3; s++) {
        float e[5];
        for (int i = 0; i < 5; i++) {
            float r = (float)i - 2.0f;
            float denom = 2.0f * (float)sig[s] * (float)sig[s];
            float ex = -(r * r) / denom;
            e[i] = (float)exp((double)ex);
        }
        float sum = (((e[0] + e[1]) + e[2]) + e[3]) + e[4];
        for (int i = 0; i < 5; i++) cf.k[s][i] = e[i] / sum;
    }

    // ---- Canny path: fused front-end, exact hysteresis, combine ----
    k_canny_front<<<dim3(16, 16, NIMG), 256>>>(x, p_Sb, p_Wb, cf);
    k_hyst<<<NIMG, 512>>>(p_Sb, p_Wb, p_Eb);
    k_combined_bits<<<(BB * WPI * 32) / 256, 256>>>(p_Eb, o_canny);

    // ---- weight transpose (co-contiguous, vec4-friendly) ----
    k_wtrans<<<7, 256>>>(wd1, wd2, wd3, wd4, wr1, wr2, wr3, p_wt);

    // ---- deep conv stack ----
    dim3 cb(32, 4), cg(WW / 32, HH / 16, BB);
    conv3x3_k<3, 16, 16, 0><<<cg, cb>>>(x,     HWC, 3 * HWC,  p_wt + 0,    bd1, p_hA, nullptr, nullptr, nullptr);
    conv3x3_k<16, 16, 16, 0><<<cg, cb>>>(p_hA, HWC, 16 * HWC, p_wt + 432,  bd2, p_hB, nullptr, nullptr, nullptr);
    conv3x3_k<16, 8, 8, 0><<<cg, cb>>>(p_hB,  HWC, 16 * HWC,  p_wt + 2736, bd3, p_hA, nullptr, nullptr, nullptr);
    conv3x3_k<8, 1, 4, 2><<<cg, cb>>>(p_hA,   HWC, 8 * HWC,   p_wt + 3888, bd4, o_deep, o_feat, nullptr, nullptr);

    // ---- refine stack: input channels = [combined_canny, deep_edges] ----
    conv3x3_k<2, 8, 8, 0><<<cg, cb>>>(o_canny, BHWC, HWC,     p_wt + 4176, br1, p_hB, nullptr, nullptr, nullptr);
    conv3x3_k<8, 4, 4, 0><<<cg, cb>>>(p_hB,   HWC, 8 * HWC,   p_wt + 4320, br2, p_hA, nullptr, nullptr, nullptr);
    conv3x3_k<4, 1, 4, 3><<<cg, cb>>>(p_hA,   HWC, 4 * HWC,   p_wt + 4608, br3, o_edge, o_feat, mask, o_deep);
}